// round 12
// baseline (speedup 1.0000x reference)
#include <cuda_runtime.h>
#include <cuda_fp16.h>
#include <cstdint>

// Radon transform: out[b, n, t] = sum_h bilinear(img_b, R(theta_n) * grid(t, h))
// B=2, N=180, H=W=512.
//
// fp16 delta-quad image + TRANSPOSED copy. For theta in (45,135) deg the warp's
// L1 footprint spans fewer storage rows when sampling the transposed image
// (row-slope becomes min(|s|,|c|)), cutting L1tex wavefronts ~14%.
// One LDG.64 per sample; 8(t)x4(h) warp tile; h-interval zero-skip; clamp-free
// interior; magic-number floor/fract; linear float-bits addressing (no masks).

#define IMG 512
#define NANG 180
#define NBATCH 2
#define QPITCH 516                    // quad row pitch; valid rows/cols 0..515
#define QELEMS (QPITCH * QPITCH)
#define MAGIC1 12582913.0f            // 2^23 + 2^22 + 1
#define MAGIC_BITS 0x4B400000u        // float bits of 12582912.0f (= magic + floor(v)+1 - that offset)
#define ROWB (QPITCH * 8u)            // 4128 bytes per quad row

__device__ uint2 d_quadN[NBATCH * QELEMS];   // normal:     (v00,v01) | (v10-v00, v11-v01)
__device__ uint2 d_quadT[NBATCH * QELEMS];   // transposed image's quads

__device__ __forceinline__ float pix(const float* img, int r, int c) {
    return ((unsigned)r < IMG && (unsigned)c < IMG) ? img[r * IMG + c] : 0.0f;
}

// Prologue: build both fp16 delta-quad images.
__global__ void quad_kernel(const float* __restrict__ x) {
    int idx = blockIdx.x * blockDim.x + threadIdx.x;
    int total = NBATCH * QELEMS;
    if (idx >= total) return;
    int b   = idx / QELEMS;
    int rem = idx - b * QELEMS;
    int r   = rem / QPITCH;    // storage row
    int cc  = rem - r * QPITCH;

    const float* img = x + b * (IMG * IMG);

    // normal: P(row=r-1+dy, col=cc-1+dx)
    {
        float v00 = pix(img, r - 1, cc - 1);
        float v10 = pix(img, r - 1, cc);
        float v01 = pix(img, r,     cc - 1);
        float v11 = pix(img, r,     cc);
        __half2 left  = __floats2half2_rn(v00, v01);
        __half2 delta = __floats2half2_rn(v10 - v00, v11 - v01);
        uint2 q;
        q.x = *(const unsigned int*)&left;
        q.y = *(const unsigned int*)&delta;
        d_quadN[idx] = q;
    }
    // transposed: Pt(y,x) = P(x,y); quadT(r,cc) corners Pt(r-1+dy, cc-1+dx)
    {
        float v00 = pix(img, cc - 1, r - 1);
        float v10 = pix(img, cc,     r - 1);
        float v01 = pix(img, cc - 1, r);
        float v11 = pix(img, cc,     r);
        __half2 left  = __floats2half2_rn(v00, v01);
        __half2 delta = __floats2half2_rn(v10 - v00, v11 - v01);
        uint2 q;
        q.x = *(const unsigned int*)&left;
        q.y = *(const unsigned int*)&delta;
        d_quadT[idx] = q;
    }
}

// X = fast (within-row) coord, Y = row coord; both must be in [-1, 512].
__device__ __forceinline__ void sample_accum(const uint2* __restrict__ quad,
                                             float X, float Y, float& acc) {
    const float fxm = __fadd_rd(X, MAGIC1);      // bits = MAGIC_BITS + (floor(X)+1)
    const float fym = __fadd_rd(Y, MAGIC1);
    const float fx = X - (fxm - MAGIC1);         // exact fract in [0,1)
    const float fy = Y - (fym - MAGIC1);

    const unsigned bx = __float_as_uint(fxm);
    const unsigned by = __float_as_uint(fym);
    // exact 32-bit offset: (floor(Y)+1)*ROWB + (floor(X)+1)*8
    const unsigned off = bx * 8u + by * ROWB + (0u - MAGIC_BITS * (ROWB + 8u));
    const uint2 q = __ldg((const uint2*)((const char*)quad + off));

    const __half2 left  = *(const __half2*)&q.x;  // (v00, v01)
    const __half2 delta = *(const __half2*)&q.y;  // (v10-v00, v11-v01)

    const __half2 fx2 = __floats2half2_rn(fx, fx);
    const __half2 tb  = __hfma2(fx2, delta, left);            // (top, bot)
    const float2  f2  = __half22float2(tb);

    acc += fmaf(fy, f2.y - f2.x, f2.x);
}

__global__ void __launch_bounds__(128) radon_kernel(const float* __restrict__ angles,
                                                    float* __restrict__ out) {
    const int warp = threadIdx.x >> 5;
    const int lane = threadIdx.x & 31;
    const int i = lane & 7;          // t within warp's 8-wide tile
    const int p = lane >> 3;         // h phase 0..3

    const int t0 = blockIdx.x * 32 + warp * 8;     // warp's first detector column
    const int t = t0 + i;
    const int n = blockIdx.y;                      // angle
    const int b = blockIdx.z;                      // batch

    const float ang = angles[n] * 0.017453292519943295f;   // deg2rad
    const float s = sinf(ang);                     // s >= 0 for 0..179 deg
    const float c = cosf(ang);
    const float ns = -s;

    // Pixel coords (unit steps): ix(t,h) = I0 + t*c - h*s ; iy(t,h) = J0 + t*s + h*c
    const float I0 = 255.5f * (s - c + 1.0f);
    const float J0 = 255.5f * (1.0f - s - c);

    const float tix0 = fmaf((float)t, c, I0);
    const float tiy0 = fmaf((float)t, s, J0);

    const float txA = fmaf((float)t0, c, I0), txB = fmaf((float)(t0 + 7), c, I0);
    const float tyA = fmaf((float)t0, s, J0), tyB = fmaf((float)(t0 + 7), s, J0);
    const float txmin = fminf(txA, txB), txmax = fmaxf(txA, txB);
    const float tymin = fminf(tyA, tyB), tymax = fmaxf(tyA, tyB);

    // ---- outer interval: SOME lane nonzero (ix,iy in (-1,512)), padded +-1 ----
    float hy0, hy1, hx0, hx1;
    if (fabsf(c) > 1e-5f) {
        const float inv = 1.0f / c;
        const float hA = (-1.0f - tymax) * inv;
        const float hB = (512.0f - tymin) * inv;
        hy0 = fminf(hA, hB); hy1 = fmaxf(hA, hB);
    } else { hy0 = 0.0f; hy1 = 511.0f; }
    if (s > 1e-5f) {
        const float inv = 1.0f / s;
        const float hA = (txmin - 512.0f) * inv;
        const float hB = (txmax + 1.0f) * inv;
        hx0 = fminf(hA, hB); hx1 = fmaxf(hA, hB);
    } else { hx0 = 0.0f; hx1 = 511.0f; }

    const int hs = __float2int_rd(fmaxf(fmaxf(hy0, hx0) - 1.0f, 0.0f));
    const int he = __float2int_ru(fminf(fminf(hy1, hx1) + 1.0f, 511.0f)) + 1;

    // ---- interior interval: ALL lanes have ix,iy in [-1,512] (clamps identity) ----
    float xlo, xhi, ylo, yhi;
    if (s > 1e-2f) {
        const float inv = 1.0f / s;
        xlo = (txmax - 512.0f) * inv;
        xhi = (txmin + 1.0f) * inv;
    } else { xlo = -1e30f; xhi = 1e30f; }
    if (fabsf(c) > 1e-2f) {
        const float inv = 1.0f / c;
        const float hA = (-1.0f - tymin) * inv;
        const float hB = (512.0f - tymax) * inv;
        ylo = fminf(hA, hB); yhi = fmaxf(hA, hB);
    } else { ylo = -1e30f; yhi = 1e30f; }

    const float ilo = fmaxf(xlo, ylo) + 0.0625f;
    const float ihi = fminf(xhi, yhi) - 0.0625f;
    int his = __float2int_ru(fminf(fmaxf(ilo, 0.0f), 520.0f));
    int hie = __float2int_rd(fminf(fmaxf(ihi, -1.0f), 511.0f)) + 1;
    his = min(max(his, hs), he);
    hie = min(max(hie, his), he);

    // ---- transpose selection: row coord gets the smaller t-slope ----
    const bool tr = (s > fabsf(c));               // theta in (45,135) deg
    const uint2* __restrict__ quad = (tr ? d_quadT : d_quadN) + b * QELEMS;
    const float X0 = tr ? tiy0 : tix0;            // fast coord
    const float dX = tr ? c    : ns;
    const float Y0 = tr ? tix0 : tiy0;            // row coord
    const float dY = tr ? ns   : c;

    float acc = 0.0f;

    // edge 1: [hs, his) with clamps
    {
        const int kmax = (his - hs - p + 3) >> 2;
        float hf = (float)(hs + p);
        for (int k = 0; k < kmax; ++k) {
            float X = fmaf(hf, dX, X0);
            float Y = fmaf(hf, dY, Y0);
            X = fminf(fmaxf(X, -1.0f), 512.0f);
            Y = fminf(fmaxf(Y, -1.0f), 512.0f);
            sample_accum(quad, X, Y, acc);
            hf += 4.0f;
        }
    }
    // interior: [his, hie) no clamps
    {
        const int kmax = (hie - his - p + 3) >> 2;
        float hf = (float)(his + p);
#pragma unroll 4
        for (int k = 0; k < kmax; ++k) {
            const float X = fmaf(hf, dX, X0);
            const float Y = fmaf(hf, dY, Y0);
            sample_accum(quad, X, Y, acc);
            hf += 4.0f;
        }
    }
    // edge 2: [hie, he) with clamps
    {
        const int kmax = (he - hie - p + 3) >> 2;
        float hf = (float)(hie + p);
        for (int k = 0; k < kmax; ++k) {
            float X = fmaf(hf, dX, X0);
            float Y = fmaf(hf, dY, Y0);
            X = fminf(fmaxf(X, -1.0f), 512.0f);
            Y = fminf(fmaxf(Y, -1.0f), 512.0f);
            sample_accum(quad, X, Y, acc);
            hf += 4.0f;
        }
    }

    // Fold the 4 h-phases (lanes p=0..3 share the same t).
    acc += __shfl_xor_sync(0xffffffffu, acc, 8);
    acc += __shfl_xor_sync(0xffffffffu, acc, 16);

    if (p == 0) {
        out[(b * NANG + n) * IMG + t] = acc;
    }
}

extern "C" void kernel_launch(void* const* d_in, const int* in_sizes, int n_in,
                              void* d_out, int out_size) {
    const float* x      = (const float*)d_in[0];   // [2,1,512,512]
    const float* angles = (const float*)d_in[1];   // [180]
    float* out          = (float*)d_out;           // [2,180,512]

    {
        int total = NBATCH * QELEMS;
        int threads = 256;
        int blocks = (total + threads - 1) / threads;
        quad_kernel<<<blocks, threads>>>(x);
    }
    {
        dim3 block(128, 1, 1);
        dim3 grid(IMG / 32, NANG, NBATCH);   // 16 x 180 x 2 = 5760 blocks
        radon_kernel<<<grid, block>>>(angles, out);
    }
}

// round 13
// speedup vs baseline: 1.2619x; 1.2619x over previous
#include <cuda_runtime.h>
#include <cuda_fp16.h>
#include <cstdint>

// Radon transform: out[b, n, t] = sum_h bilinear(img_b, R(theta_n) * grid(t, h))
// B=2, N=180, H=W=512.
//
// BATCH-FUSED fp16 delta-quad image (+ transposed copy): both batches sample the
// exact same coordinates, so each 16B quad packs (b0.left, b0.delta, b1.left,
// b1.delta) and ONE LDG.128 serves both batches -> warp-iterations halve and all
// coordinate/index math is shared. Transposed copy keeps the warp's L1 footprint
// row-slope at min(|s|,|c|). Magic-number floor/fract, clamp-free interior,
// per-(angle,t-tile) h-interval zero skip, 8(t)x4(h) warp tile.

#define IMG 512
#define NANG 180
#define QPITCH 516                    // quad row pitch; valid rows/cols 0..515
#define QELEMS (QPITCH * QPITCH)
#define MAGIC1 12582913.0f            // 2^23 + 2^22 + 1
#define MAGIC_BITS 0x4B400000u        // float bits of 12582912.0f
#define QROWB (QPITCH * 16u)          // 8256 bytes per quad row (uint4 quads)

__device__ uint4 d_quadN[QELEMS];     // (b0 v00,v01)|(b0 dT,dB)|(b1 v00,v01)|(b1 dT,dB)
__device__ uint4 d_quadT[QELEMS];     // transposed-image quads, same packing

__device__ __forceinline__ float pix(const float* img, int r, int c) {
    return ((unsigned)r < IMG && (unsigned)c < IMG) ? img[r * IMG + c] : 0.0f;
}

__device__ __forceinline__ unsigned packh2(float a, float b) {
    __half2 h = __floats2half2_rn(a, b);
    return *(const unsigned int*)&h;
}

// Prologue: for each quad cell read the 4 corner pixels of both batches ONCE and
// emit both the normal quad and the transposed quad (transposed via the write
// index — stores don't stall, so no strided reads anywhere).
__global__ void quad_kernel(const float* __restrict__ x) {
    int idx = blockIdx.x * blockDim.x + threadIdx.x;
    if (idx >= QELEMS) return;
    int r  = idx / QPITCH;    // storage row
    int cc = idx - r * QPITCH;

    const float* img0 = x;
    const float* img1 = x + IMG * IMG;

    // corners P(r-1+dy, cc-1+dx) for both batches
    float a00 = pix(img0, r - 1, cc - 1), a10 = pix(img0, r - 1, cc);
    float a01 = pix(img0, r,     cc - 1), a11 = pix(img0, r,     cc);
    float b00 = pix(img1, r - 1, cc - 1), b10 = pix(img1, r - 1, cc);
    float b01 = pix(img1, r,     cc - 1), b11 = pix(img1, r,     cc);

    // normal quad at (r, cc): left=(v00,v01), delta=(v10-v00, v11-v01)
    uint4 qn;
    qn.x = packh2(a00, a01);
    qn.y = packh2(a10 - a00, a11 - a01);
    qn.z = packh2(b00, b01);
    qn.w = packh2(b10 - b00, b11 - b01);
    d_quadN[idx] = qn;

    // transposed image quad lives at (cc, r): its corners are the SAME pixels with
    // the roles of dx/dy swapped: left=(v00,v10), delta=(v01-v00, v11-v10)
    uint4 qt;
    qt.x = packh2(a00, a10);
    qt.y = packh2(a01 - a00, a11 - a10);
    qt.z = packh2(b00, b10);
    qt.w = packh2(b01 - b00, b11 - b10);
    d_quadT[cc * QPITCH + r] = qt;
}

// X = fast (within-row) coord, Y = row coord; both must be in [-1, 512].
__device__ __forceinline__ void sample_accum(const uint4* __restrict__ quad,
                                             float X, float Y,
                                             float& acc0, float& acc1) {
    const float fxm = __fadd_rd(X, MAGIC1);      // bits = MAGIC_BITS + (floor(X)+1)
    const float fym = __fadd_rd(Y, MAGIC1);
    const float fx = X - (fxm - MAGIC1);         // exact fract in [0,1)
    const float fy = Y - (fym - MAGIC1);

    const unsigned bx = __float_as_uint(fxm);
    const unsigned by = __float_as_uint(fym);
    // exact 32-bit offset: (floor(Y)+1)*QROWB + (floor(X)+1)*16
    const unsigned off = bx * 16u + by * QROWB + (0u - MAGIC_BITS * (QROWB + 16u));
    const uint4 q = __ldg((const uint4*)((const char*)quad + off));

    const __half2 fx2 = __floats2half2_rn(fx, fx);

    const __half2 tb0 = __hfma2(fx2, *(const __half2*)&q.y, *(const __half2*)&q.x);
    const float2  f0  = __half22float2(tb0);
    acc0 += fmaf(fy, f0.y - f0.x, f0.x);

    const __half2 tb1 = __hfma2(fx2, *(const __half2*)&q.w, *(const __half2*)&q.z);
    const float2  f1  = __half22float2(tb1);
    acc1 += fmaf(fy, f1.y - f1.x, f1.x);
}

__global__ void __launch_bounds__(128) radon_kernel(const float* __restrict__ angles,
                                                    float* __restrict__ out) {
    const int warp = threadIdx.x >> 5;
    const int lane = threadIdx.x & 31;
    const int i = lane & 7;          // t within warp's 8-wide tile
    const int p = lane >> 3;         // h phase 0..3

    const int t0 = blockIdx.x * 32 + warp * 8;     // warp's first detector column
    const int t = t0 + i;
    const int n = blockIdx.y;                      // angle

    const float ang = angles[n] * 0.017453292519943295f;   // deg2rad
    const float s = sinf(ang);                     // s >= 0 for 0..179 deg
    const float c = cosf(ang);
    const float ns = -s;

    // Pixel coords (unit steps): ix(t,h) = I0 + t*c - h*s ; iy(t,h) = J0 + t*s + h*c
    const float I0 = 255.5f * (s - c + 1.0f);
    const float J0 = 255.5f * (1.0f - s - c);

    const float tix0 = fmaf((float)t, c, I0);
    const float tiy0 = fmaf((float)t, s, J0);

    const float txA = fmaf((float)t0, c, I0), txB = fmaf((float)(t0 + 7), c, I0);
    const float tyA = fmaf((float)t0, s, J0), tyB = fmaf((float)(t0 + 7), s, J0);
    const float txmin = fminf(txA, txB), txmax = fmaxf(txA, txB);
    const float tymin = fminf(tyA, tyB), tymax = fmaxf(tyA, tyB);

    // ---- outer interval: SOME lane nonzero (ix,iy in (-1,512)), padded +-1 ----
    float hy0, hy1, hx0, hx1;
    if (fabsf(c) > 1e-5f) {
        const float inv = 1.0f / c;
        const float hA = (-1.0f - tymax) * inv;
        const float hB = (512.0f - tymin) * inv;
        hy0 = fminf(hA, hB); hy1 = fmaxf(hA, hB);
    } else { hy0 = 0.0f; hy1 = 511.0f; }
    if (s > 1e-5f) {
        const float inv = 1.0f / s;
        const float hA = (txmin - 512.0f) * inv;
        const float hB = (txmax + 1.0f) * inv;
        hx0 = fminf(hA, hB); hx1 = fmaxf(hA, hB);
    } else { hx0 = 0.0f; hx1 = 511.0f; }

    const int hs = __float2int_rd(fmaxf(fmaxf(hy0, hx0) - 1.0f, 0.0f));
    const int he = __float2int_ru(fminf(fminf(hy1, hx1) + 1.0f, 511.0f)) + 1;

    // ---- interior interval: ALL lanes have ix,iy in [-1,512] (clamps identity) ----
    float xlo, xhi, ylo, yhi;
    if (s > 1e-2f) {
        const float inv = 1.0f / s;
        xlo = (txmax - 512.0f) * inv;
        xhi = (txmin + 1.0f) * inv;
    } else { xlo = -1e30f; xhi = 1e30f; }
    if (fabsf(c) > 1e-2f) {
        const float inv = 1.0f / c;
        const float hA = (-1.0f - tymin) * inv;
        const float hB = (512.0f - tymax) * inv;
        ylo = fminf(hA, hB); yhi = fmaxf(hA, hB);
    } else { ylo = -1e30f; yhi = 1e30f; }

    const float ilo = fmaxf(xlo, ylo) + 0.0625f;
    const float ihi = fminf(xhi, yhi) - 0.0625f;
    int his = __float2int_ru(fminf(fmaxf(ilo, 0.0f), 520.0f));
    int hie = __float2int_rd(fminf(fmaxf(ihi, -1.0f), 511.0f)) + 1;
    his = min(max(his, hs), he);
    hie = min(max(hie, his), he);

    // ---- transpose selection: row coord gets the smaller t-slope ----
    const bool tr = (s > fabsf(c));               // theta in (45,135) deg
    const uint4* __restrict__ quad = tr ? d_quadT : d_quadN;
    const float X0 = tr ? tiy0 : tix0;            // fast coord
    const float dX = tr ? c    : ns;
    const float Y0 = tr ? tix0 : tiy0;            // row coord
    const float dY = tr ? ns   : c;

    float acc0 = 0.0f, acc1 = 0.0f;

    // edge 1: [hs, his) with clamps
    {
        const int kmax = (his - hs - p + 3) >> 2;
        float hf = (float)(hs + p);
        for (int k = 0; k < kmax; ++k) {
            float X = fmaf(hf, dX, X0);
            float Y = fmaf(hf, dY, Y0);
            X = fminf(fmaxf(X, -1.0f), 512.0f);
            Y = fminf(fmaxf(Y, -1.0f), 512.0f);
            sample_accum(quad, X, Y, acc0, acc1);
            hf += 4.0f;
        }
    }
    // interior: [his, hie) no clamps
    {
        const int kmax = (hie - his - p + 3) >> 2;
        float hf = (float)(his + p);
#pragma unroll 4
        for (int k = 0; k < kmax; ++k) {
            const float X = fmaf(hf, dX, X0);
            const float Y = fmaf(hf, dY, Y0);
            sample_accum(quad, X, Y, acc0, acc1);
            hf += 4.0f;
        }
    }
    // edge 2: [hie, he) with clamps
    {
        const int kmax = (he - hie - p + 3) >> 2;
        float hf = (float)(hie + p);
        for (int k = 0; k < kmax; ++k) {
            float X = fmaf(hf, dX, X0);
            float Y = fmaf(hf, dY, Y0);
            X = fminf(fmaxf(X, -1.0f), 512.0f);
            Y = fminf(fmaxf(Y, -1.0f), 512.0f);
            sample_accum(quad, X, Y, acc0, acc1);
            hf += 4.0f;
        }
    }

    // Fold the 4 h-phases (lanes p=0..3 share the same t).
    acc0 += __shfl_xor_sync(0xffffffffu, acc0, 8);
    acc0 += __shfl_xor_sync(0xffffffffu, acc0, 16);
    acc1 += __shfl_xor_sync(0xffffffffu, acc1, 8);
    acc1 += __shfl_xor_sync(0xffffffffu, acc1, 16);

    if (p == 0) {
        out[n * IMG + t] = acc0;                       // batch 0
        out[(NANG + n) * IMG + t] = acc1;              // batch 1
    }
}

extern "C" void kernel_launch(void* const* d_in, const int* in_sizes, int n_in,
                              void* d_out, int out_size) {
    const float* x      = (const float*)d_in[0];   // [2,1,512,512]
    const float* angles = (const float*)d_in[1];   // [180]
    float* out          = (float*)d_out;           // [2,180,512]

    {
        int threads = 256;
        int blocks = (QELEMS + threads - 1) / threads;
        quad_kernel<<<blocks, threads>>>(x);
    }
    {
        dim3 block(128, 1, 1);
        dim3 grid(IMG / 32, NANG, 1);   // 16 x 180 blocks, both batches fused
        radon_kernel<<<grid, block>>>(angles, out);
    }
}

// round 15
// speedup vs baseline: 1.4052x; 1.1135x over previous
#include <cuda_runtime.h>
#include <cuda_fp16.h>
#include <cstdint>

// Radon transform: out[b, n, t] = sum_h bilinear(img_b, R(theta_n) * grid(t, h))
// B=2, N=180 (angles = 0..179 deg), H=W=512.
//
// BATCH + ANGLE fusion: batches share coordinates (R13), and theta+90's samples
// are the same lattice via (ix',iy') = (511-iy, ix):
//   B(img; 511-iy, ix) = B(img2; ix, iy),  img2(r,c) = img(c, 511-r).
// So each warp-iteration computes 4 outputs (2 batches x {theta, theta+90}) from
// 2 LDG.128 (batch-packed fp16 delta-quads of img and img2) with ALL coordinate,
// floor/fract and address math shared. Transposed copies keep the L1 footprint
// row-slope at min(|s|,|c|). Grid = 1440 blocks -> single wave, no tail.

#define IMG 512
#define NANG 180
#define QPITCH 516                    // quad row pitch; valid rows/cols 0..515
#define QELEMS (QPITCH * QPITCH)
#define MAGIC1 12582913.0f            // 2^23 + 2^22 + 1
#define MAGIC_BITS 0x4B400000u        // float bits of 12582912.0f
#define QROWB (QPITCH * 16u)          // bytes per quad row

__device__ uint4 d_quadN [QELEMS];    // img  pair, normal
__device__ uint4 d_quadT [QELEMS];    // img  pair, transposed
__device__ uint4 d_quadN2[QELEMS];    // img2 pair, normal   (img2(r,c)=img(c,511-r))
__device__ uint4 d_quadT2[QELEMS];    // img2 pair, transposed

__device__ __forceinline__ float pix(const float* img, int r, int c) {
    return ((unsigned)r < IMG && (unsigned)c < IMG) ? img[r * IMG + c] : 0.0f;
}
__device__ __forceinline__ unsigned packh2(float a, float b) {
    __half2 h = __floats2half2_rn(a, b);
    return *(const unsigned int*)&h;
}

// Prologue: read the 4 corner pixels of both batches once per cell; emit all 4
// quad arrays by index remapping (scattered writes are fire-and-forget).
__global__ void quad_kernel(const float* __restrict__ x) {
    int idx = blockIdx.x * blockDim.x + threadIdx.x;
    if (idx >= QELEMS) return;
    int r  = idx / QPITCH;    // storage row
    int cc = idx - r * QPITCH;

    const float* img0 = x;
    const float* img1 = x + IMG * IMG;

    float a00 = pix(img0, r - 1, cc - 1), a10 = pix(img0, r - 1, cc);
    float a01 = pix(img0, r,     cc - 1), a11 = pix(img0, r,     cc);
    float b00 = pix(img1, r - 1, cc - 1), b10 = pix(img1, r - 1, cc);
    float b01 = pix(img1, r,     cc - 1), b11 = pix(img1, r,     cc);

    // img normal quad at (r, cc): left=(c00,c01), delta=(c10-c00, c11-c01)
    {
        uint4 q;
        q.x = packh2(a00, a01); q.y = packh2(a10 - a00, a11 - a01);
        q.z = packh2(b00, b01); q.w = packh2(b10 - b00, b11 - b01);
        d_quadN[idx] = q;
    }
    // img transposed quad at (cc, r)
    {
        uint4 q;
        q.x = packh2(a00, a10); q.y = packh2(a01 - a00, a11 - a10);
        q.z = packh2(b00, b10); q.w = packh2(b01 - b00, b11 - b10);
        d_quadT[cc * QPITCH + r] = q;
    }
    // img2 cell (rq=512-cc, cq=r): corners c2(dy,dx) = img[r-1+dx][cc-dy]
    //   c2(0,0)=a10  c2(0,1)=a11  c2(1,0)=a00  c2(1,1)=a01   (batch1: b**)
    int rq = 512 - cc;
    if (rq >= 0) {
        {   // img2 normal at (rq, cq=r)
            uint4 q;
            q.x = packh2(a10, a00); q.y = packh2(a11 - a10, a01 - a00);
            q.z = packh2(b10, b00); q.w = packh2(b11 - b10, b01 - b00);
            d_quadN2[rq * QPITCH + r] = q;
        }
        {   // img2 transposed at (r, rq)
            uint4 q;
            q.x = packh2(a10, a11); q.y = packh2(a00 - a10, a01 - a11);
            q.z = packh2(b10, b11); q.w = packh2(b00 - b10, b01 - b11);
            d_quadT2[r * QPITCH + rq] = q;
        }
    }
    // img2 rows/cols 513..515 are all-zero cells not covered by the map above.
    if (cc < 3) {
        int e = 513 + cc;
        uint4 z = make_uint4(0u, 0u, 0u, 0u);
        d_quadN2[e * QPITCH + r] = z;
        d_quadT2[r * QPITCH + e] = z;
    }
}

// X = fast coord, Y = row coord; both in [-1, 512]. One iteration -> 4 outputs.
__device__ __forceinline__ void sample_accum4(const uint4* __restrict__ qA,
                                              const uint4* __restrict__ qB,
                                              float X, float Y,
                                              float& acc0, float& acc1,
                                              float& acc2, float& acc3) {
    const float fxm = __fadd_rd(X, MAGIC1);
    const float fym = __fadd_rd(Y, MAGIC1);
    const float fx = X - (fxm - MAGIC1);
    const float fy = Y - (fym - MAGIC1);

    const unsigned bx = __float_as_uint(fxm);
    const unsigned by = __float_as_uint(fym);
    const unsigned off = bx * 16u + by * QROWB + (0u - MAGIC_BITS * (QROWB + 16u));

    const uint4 q  = __ldg((const uint4*)((const char*)qA + off));
    const uint4 q2 = __ldg((const uint4*)((const char*)qB + off));

    const __half2 fx2 = __floats2half2_rn(fx, fx);

    {   const __half2 tb = __hfma2(fx2, *(const __half2*)&q.y, *(const __half2*)&q.x);
        const float2 f = __half22float2(tb);
        acc0 += fmaf(fy, f.y - f.x, f.x); }
    {   const __half2 tb = __hfma2(fx2, *(const __half2*)&q.w, *(const __half2*)&q.z);
        const float2 f = __half22float2(tb);
        acc1 += fmaf(fy, f.y - f.x, f.x); }
    {   const __half2 tb = __hfma2(fx2, *(const __half2*)&q2.y, *(const __half2*)&q2.x);
        const float2 f = __half22float2(tb);
        acc2 += fmaf(fy, f.y - f.x, f.x); }
    {   const __half2 tb = __hfma2(fx2, *(const __half2*)&q2.w, *(const __half2*)&q2.z);
        const float2 f = __half22float2(tb);
        acc3 += fmaf(fy, f.y - f.x, f.x); }
}

__global__ void __launch_bounds__(128, 10) radon_kernel(const float* __restrict__ angles,
                                                        float* __restrict__ out) {
    const int warp = threadIdx.x >> 5;
    const int lane = threadIdx.x & 31;
    const int i = lane & 7;          // t within warp's 8-wide tile
    const int p = lane >> 3;         // h phase 0..3

    const int t0 = blockIdx.x * 32 + warp * 8;
    const int t = t0 + i;
    const int n = blockIdx.y;        // angle pair: theta = angles[n], theta+90 = angles[n+90]

    const float ang = angles[n] * 0.017453292519943295f;
    const float s = sinf(ang);                     // theta in [0,90): s >= 0, c > 0
    const float c = cosf(ang);
    const float ns = -s;

    const float I0 = 255.5f * (s - c + 1.0f);
    const float J0 = 255.5f * (1.0f - s - c);

    const float tix0 = fmaf((float)t, c, I0);
    const float tiy0 = fmaf((float)t, s, J0);

    const float txA = fmaf((float)t0, c, I0), txB = fmaf((float)(t0 + 7), c, I0);
    const float tyA = fmaf((float)t0, s, J0), tyB = fmaf((float)(t0 + 7), s, J0);
    const float txmin = fminf(txA, txB), txmax = fmaxf(txA, txB);
    const float tymin = fminf(tyA, tyB), tymax = fmaxf(tyA, tyB);

    // ---- outer interval: SOME lane nonzero (ix,iy in (-1,512)), padded +-1 ----
    float hy0, hy1, hx0, hx1;
    if (fabsf(c) > 1e-5f) {
        const float inv = 1.0f / c;
        const float hA = (-1.0f - tymax) * inv;
        const float hB = (512.0f - tymin) * inv;
        hy0 = fminf(hA, hB); hy1 = fmaxf(hA, hB);
    } else { hy0 = 0.0f; hy1 = 511.0f; }
    if (s > 1e-5f) {
        const float inv = 1.0f / s;
        const float hA = (txmin - 512.0f) * inv;
        const float hB = (txmax + 1.0f) * inv;
        hx0 = fminf(hA, hB); hx1 = fmaxf(hA, hB);
    } else { hx0 = 0.0f; hx1 = 511.0f; }

    const int hs = __float2int_rd(fmaxf(fmaxf(hy0, hx0) - 1.0f, 0.0f));
    const int he = __float2int_ru(fminf(fminf(hy1, hx1) + 1.0f, 511.0f)) + 1;

    // ---- interior interval: ALL lanes in [-1,512] (clamps identity) ----
    float xlo, xhi, ylo, yhi;
    if (s > 1e-2f) {
        const float inv = 1.0f / s;
        xlo = (txmax - 512.0f) * inv;
        xhi = (txmin + 1.0f) * inv;
    } else { xlo = -1e30f; xhi = 1e30f; }
    if (fabsf(c) > 1e-2f) {
        const float inv = 1.0f / c;
        const float hA = (-1.0f - tymin) * inv;
        const float hB = (512.0f - tymax) * inv;
        ylo = fminf(hA, hB); yhi = fmaxf(hA, hB);
    } else { ylo = -1e30f; yhi = 1e30f; }

    const float ilo = fmaxf(xlo, ylo) + 0.0625f;
    const float ihi = fminf(xhi, yhi) - 0.0625f;
    int his = __float2int_ru(fminf(fmaxf(ilo, 0.0f), 520.0f));
    int hie = __float2int_rd(fminf(fmaxf(ihi, -1.0f), 511.0f)) + 1;
    his = min(max(his, hs), he);
    hie = min(max(hie, his), he);

    // ---- transpose selection: row coord gets the smaller t-slope ----
    const bool tr = (s > fabsf(c));
    const uint4* __restrict__ qA = tr ? d_quadT  : d_quadN;   // img  pair
    const uint4* __restrict__ qB = tr ? d_quadT2 : d_quadN2;  // img2 pair
    const float X0 = tr ? tiy0 : tix0;
    const float dX = tr ? c    : ns;
    const float Y0 = tr ? tix0 : tiy0;
    const float dY = tr ? ns   : c;

    float acc0 = 0.0f, acc1 = 0.0f, acc2 = 0.0f, acc3 = 0.0f;

    // edge 1: [hs, his) with clamps
    {
        const int kmax = (his - hs - p + 3) >> 2;
        float hf = (float)(hs + p);
        for (int k = 0; k < kmax; ++k) {
            float X = fmaf(hf, dX, X0);
            float Y = fmaf(hf, dY, Y0);
            X = fminf(fmaxf(X, -1.0f), 512.0f);
            Y = fminf(fmaxf(Y, -1.0f), 512.0f);
            sample_accum4(qA, qB, X, Y, acc0, acc1, acc2, acc3);
            hf += 4.0f;
        }
    }
    // interior: [his, hie) no clamps
    {
        const int kmax = (hie - his - p + 3) >> 2;
        float hf = (float)(his + p);
#pragma unroll 4
        for (int k = 0; k < kmax; ++k) {
            const float X = fmaf(hf, dX, X0);
            const float Y = fmaf(hf, dY, Y0);
            sample_accum4(qA, qB, X, Y, acc0, acc1, acc2, acc3);
            hf += 4.0f;
        }
    }
    // edge 2: [hie, he) with clamps
    {
        const int kmax = (he - hie - p + 3) >> 2;
        float hf = (float)(hie + p);
        for (int k = 0; k < kmax; ++k) {
            float X = fmaf(hf, dX, X0);
            float Y = fmaf(hf, dY, Y0);
            X = fminf(fmaxf(X, -1.0f), 512.0f);
            Y = fminf(fmaxf(Y, -1.0f), 512.0f);
            sample_accum4(qA, qB, X, Y, acc0, acc1, acc2, acc3);
            hf += 4.0f;
        }
    }

    // Fold the 4 h-phases.
    acc0 += __shfl_xor_sync(0xffffffffu, acc0, 8);
    acc0 += __shfl_xor_sync(0xffffffffu, acc0, 16);
    acc1 += __shfl_xor_sync(0xffffffffu, acc1, 8);
    acc1 += __shfl_xor_sync(0xffffffffu, acc1, 16);
    acc2 += __shfl_xor_sync(0xffffffffu, acc2, 8);
    acc2 += __shfl_xor_sync(0xffffffffu, acc2, 16);
    acc3 += __shfl_xor_sync(0xffffffffu, acc3, 8);
    acc3 += __shfl_xor_sync(0xffffffffu, acc3, 16);

    if (p == 0) {
        out[n * IMG + t] = acc0;                        // b0, theta
        out[(NANG + n) * IMG + t] = acc1;               // b1, theta
        out[(n + 90) * IMG + t] = acc2;                 // b0, theta+90
        out[(NANG + n + 90) * IMG + t] = acc3;          // b1, theta+90
    }
}

extern "C" void kernel_launch(void* const* d_in, const int* in_sizes, int n_in,
                              void* d_out, int out_size) {
    const float* x      = (const float*)d_in[0];   // [2,1,512,512]
    const float* angles = (const float*)d_in[1];   // [180]
    float* out          = (float*)d_out;           // [2,180,512]

    {
        int threads = 256;
        int blocks = (QELEMS + threads - 1) / threads;
        quad_kernel<<<blocks, threads>>>(x);
    }
    {
        dim3 block(128, 1, 1);
        dim3 grid(IMG / 32, 90, 1);   // 16 x 90 = 1440 blocks, 4 outputs per warp-unit
        radon_kernel<<<grid, block>>>(angles, out);
    }
}